// round 8
// baseline (speedup 1.0000x reference)
#include <cuda_runtime.h>
#include <cstdint>

#define T_STEPS 65536
#define HID     128
#define INS     96
#define LINW    32
#define G3      384   // 3 * HID

// Scratch (allocation-free rule: __device__ globals)
__device__ float g_igates[(size_t)(T_STEPS + 1) * G3];  // +1 row pad for the t+1 prefetch
__device__ float g_hbuf[(size_t)T_STEPS * LINW];

typedef unsigned long long ull;

// ---- packed f32x2 helpers (Blackwell sm_103a) ----
__device__ __forceinline__ ull pack2(float lo, float hi) {
    ull r; asm("mov.b64 %0,{%1,%2};" : "=l"(r) : "f"(lo), "f"(hi)); return r;
}
__device__ __forceinline__ void unpack2(ull p, float& lo, float& hi) {
    asm("mov.b64 {%0,%1},%2;" : "=f"(lo), "=f"(hi) : "l"(p));
}
__device__ __forceinline__ ull ffma2(ull a, ull b, ull c) {
    ull d; asm("fma.rn.f32x2 %0,%1,%2,%3;" : "=l"(d) : "l"(a), "l"(b), "l"(c)); return d;
}
__device__ __forceinline__ ull fadd2(ull a, ull b) {
    ull d; asm("add.rn.f32x2 %0,%1,%2;" : "=l"(d) : "l"(a), "l"(b)); return d;
}

// ---- fast, overflow-safe activations (err ~1e-6, well under 1e-3 budget) ----
__device__ __forceinline__ float fsigmoid(float x) {
    float e = __expf(-x);
    return __fdividef(1.0f, 1.0f + e);
}
__device__ __forceinline__ float ftanh_f(float x) {
    float ax = fabsf(x);
    float e  = __expf(-2.0f * ax);
    float t  = __fdividef(1.0f - e, 1.0f + e);
    return copysignf(t, x);
}

// ---- cluster / mbarrier helpers ----
__device__ __forceinline__ uint32_t s2u(const void* p) {
    uint32_t a;
    asm("{ .reg .u64 t; cvta.to.shared.u64 t, %1; cvt.u32.u64 %0, t; }" : "=r"(a) : "l"(p));
    return a;
}
__device__ __forceinline__ uint32_t mapa_u32(uint32_t a, uint32_t rank) {
    uint32_t d;
    asm("mapa.shared::cluster.u32 %0, %1, %2;" : "=r"(d) : "r"(a), "r"(rank));
    return d;
}
__device__ __forceinline__ void mbar_wait_cluster(uint32_t mbar, uint32_t parity) {
    asm volatile(
        "{\n\t"
        ".reg .pred P;\n\t"
        "WL%=:\n\t"
        "mbarrier.try_wait.parity.acquire.cluster.shared::cta.b64 P, [%0], %1, 0x989680;\n\t"
        "@P bra WD%=;\n\t"
        "bra WL%=;\n\t"
        "WD%=:\n\t"
        "}"
        :: "r"(mbar), "r"(parity) : "memory");
}

// ============================================================================
// Kernel A: igates[t][j] = b_ih[j] + sum_k input_GRU[t][k] * w_ih[j][k]
// ============================================================================
__global__ __launch_bounds__(384, 1) void igates_kernel(
    const float* __restrict__ in_gru,
    const float* __restrict__ w_ih,
    const float* __restrict__ b_ih)
{
    __shared__ __align__(16) float s_in[64 * INS];
    const int tid = threadIdx.x;
    const int t0  = blockIdx.x * 64;

    {
        const float4* gsrc = (const float4*)(in_gru + (size_t)t0 * INS);
        float4* sdst = (float4*)s_in;
        for (int q = tid; q < (64 * INS) / 4; q += 384) sdst[q] = gsrc[q];
    }

    ull wq[48];
    {
        const float4* wr = (const float4*)(w_ih + (size_t)tid * INS);
        #pragma unroll
        for (int q = 0; q < 24; q++) {
            float4 v = wr[q];
            wq[2 * q]     = pack2(v.x, v.y);
            wq[2 * q + 1] = pack2(v.z, v.w);
        }
    }
    const float bias = b_ih[tid];
    __syncthreads();

    for (int tt = 0; tt < 64; tt++) {
        const ulonglong2* hp2 = (const ulonglong2*)(s_in + tt * INS);
        ull a0 = 0ull, a1 = 0ull, a2 = 0ull, a3 = 0ull;
        #pragma unroll
        for (int q = 0; q < 24; q++) {
            ulonglong2 hv = hp2[q];
            if (q & 1) { a2 = ffma2(wq[2 * q], hv.x, a2); a3 = ffma2(wq[2 * q + 1], hv.y, a3); }
            else       { a0 = ffma2(wq[2 * q], hv.x, a0); a1 = ffma2(wq[2 * q + 1], hv.y, a1); }
        }
        ull s = fadd2(fadd2(a0, a2), fadd2(a1, a3));
        float lo, hi; unpack2(s, lo, hi);
        g_igates[(size_t)(t0 + tt) * G3 + tid] = lo + hi + bias;
    }
}

// ============================================================================
// Kernel B: sequential scan on a 2-CTA CLUSTER (2 SMs).
//
// CTA c owns rows {g*128 + c*64 + j : g=0..2, j=0..63} of w_hh (192 rows) —
// exactly the (hr,hz,hn) needed to activate units u in [c*64, c*64+64).
// Per step:
//   wait peer h-half (ping-pong mbarrier, 64 arrivals) [t>0]
//   FMA: 384 threads, lane pairs (even=cols 0..63, odd=cols 64..127) per row,
//        shfl_xor merge; h in SMEM with +16B pad so even/odd broadcast
//        groups hit disjoint banks (1 wavefront per LDS.128)
//   barA -> act on 64 local units -> local STS h-half +
//        st.shared::cluster of h-half into peer (double-buffered) +
//        mbarrier.arrive.release.cluster  -> barB
// ============================================================================
__global__ __launch_bounds__(384, 1) __cluster_dims__(2, 1, 1)
void scan_kernel(
    const float* __restrict__ init_h,
    const float* __restrict__ w_hh,
    const float* __restrict__ b_n)
{
    // h layout per buffer: cols 0..63 at floats [0,64); cols 64..127 at [68,132)
    __shared__ __align__(16) float h_sm[2][136];
    __shared__ __align__(16) float hg_s[64 * 4];   // (hr,hz,hn,pad) per local unit
    __shared__ __align__(8)  ull   mbar[2];

    const int tid = threadIdx.x;
    uint32_t crank; asm("mov.u32 %0, %%cluster_ctarank;" : "=r"(crank));
    const int c = (int)crank;

    if (tid == 0) {
        asm volatile("mbarrier.init.shared.b64 [%0], 64;" :: "r"(s2u(&mbar[0])) : "memory");
        asm volatile("mbarrier.init.shared.b64 [%0], 64;" :: "r"(s2u(&mbar[1])) : "memory");
    }
    __syncthreads();
    asm volatile("barrier.cluster.arrive.aligned;" ::: "memory");
    asm volatile("barrier.cluster.wait.aligned;" ::: "memory");

    // ---- row / half assignment ----
    const int w    = tid >> 5, l = tid & 31;
    const int k    = l >> 1,  half = l & 1;
    const int rl   = w * 16 + k;          // local row 0..191
    const int gg   = rl >> 6;             // gate 0..2
    const int jj   = rl & 63;             // local unit
    const int R    = gg * 128 + c * 64 + jj;   // global w_hh row
    const uint32_t hbytes = half ? 272u : 0u;  // col-half byte base within h buffer

    // weights: 64 columns of row R -> 32 packed f32x2
    ull wq[32];
    {
        const float4* wr = (const float4*)(w_hh + (size_t)R * HID + half * 64);
        #pragma unroll
        for (int q = 0; q < 16; q++) {
            float4 v = wr[q];
            wq[2 * q]     = pack2(v.x, v.y);
            wq[2 * q + 1] = pack2(v.z, v.w);
        }
    }

    // init h_buf[0] with full init_h (both CTAs keep a full local copy)
    if (tid < HID) {
        int idx = tid + ((tid >> 6) << 2);
        h_sm[0][idx] = init_h[tid];
    }

    // act-thread state
    float bni = 0.0f, ir = 0.0f, iz = 0.0f, inq = 0.0f, h_old = 0.0f;
    uint32_t rem_h[2] = {0, 0}, rem_mb[2] = {0, 0};
    int myidx = 0;
    if (tid < 64) {
        const int u = c * 64 + tid;
        myidx = u + ((u >> 6) << 2);
        bni   = b_n[u];
        h_old = init_h[u];
        ir  = g_igates[u];
        iz  = g_igates[128 + u];
        inq = g_igates[256 + u];
        const uint32_t peer = crank ^ 1u;
        rem_h[0]  = mapa_u32(s2u(&h_sm[0][myidx]), peer);
        rem_h[1]  = mapa_u32(s2u(&h_sm[1][myidx]), peer);
        rem_mb[0] = mapa_u32(s2u(&mbar[0]), peer);
        rem_mb[1] = mapa_u32(s2u(&mbar[1]), peer);
    }
    const uint32_t mb0 = s2u(&mbar[0]), mb1 = s2u(&mbar[1]);
    int par0 = 0, par1 = 0;
    __syncthreads();

    for (int t = 0; t < T_STEPS; t++) {
        // prefetch igates for step t+1 (latency hidden behind wait + FMA)
        float irn = 0.0f, izn = 0.0f, inn = 0.0f;
        if (tid < 64) {
            const float* nx = g_igates + (size_t)(t + 1) * G3 + c * 64 + tid;
            irn = nx[0]; izn = nx[128]; inn = nx[256];
        }

        // wait for peer's h-half of step t (arrived during peer's act of t-1)
        if (t > 0) {
            if (t & 1) { mbar_wait_cluster(mb1, (uint32_t)par1); par1 ^= 1; }
            else       { mbar_wait_cluster(mb0, (uint32_t)par0); par0 ^= 1; }
        }

        // ---- FMA phase: partial dot over this thread's 64 columns ----
        {
            const ulonglong2* hp =
                (const ulonglong2*)((const char*)&h_sm[t & 1][0] + hbytes);
            ull a0 = 0ull, a1 = 0ull, a2 = 0ull, a3 = 0ull;
            #pragma unroll
            for (int q = 0; q < 16; q++) {
                ulonglong2 hv = hp[q];
                if (q & 1) { a2 = ffma2(wq[2 * q], hv.x, a2); a3 = ffma2(wq[2 * q + 1], hv.y, a3); }
                else       { a0 = ffma2(wq[2 * q], hv.x, a0); a1 = ffma2(wq[2 * q + 1], hv.y, a1); }
            }
            ull s = fadd2(fadd2(a0, a2), fadd2(a1, a3));
            float lo, hi; unpack2(s, lo, hi);
            float part  = lo + hi;
            float other = __shfl_xor_sync(0xFFFFFFFFu, part, 1);
            if (half == 0) hg_s[jj * 4 + gg] = part + other;
        }
        __syncthreads();   // barA: local hgates ready

        // ---- activation for local 64 units ----
        if (tid < 64) {
            float4 hg = *(const float4*)&hg_s[tid * 4];     // (hr, hz, hn, -)
            float r = fsigmoid(ir + hg.x);
            float z = fsigmoid(iz + hg.y);
            float n = ftanh_f(inq + r * (hg.z + bni));
            float hnew = n + z * (h_old - n);               // equinox GRUCell
            h_old = hnew;
            const int b2 = (t + 1) & 1;
            h_sm[b2][myidx] = hnew;                         // local half
            if (t < T_STEPS - 1) {
                asm volatile("st.shared::cluster.f32 [%0], %1;"
                             :: "r"(rem_h[b2]), "f"(hnew) : "memory");
                asm volatile("mbarrier.arrive.release.cluster.shared::cluster.b64 _, [%0];"
                             :: "r"(rem_mb[b2]) : "memory");
            }
            if (c == 0 && tid < LINW) g_hbuf[(size_t)t * LINW + tid] = hnew;
            ir = irn; iz = izn; inq = inn;
        }
        __syncthreads();   // barB: local h-half visible to all local warps
    }
}

// ============================================================================
// Kernel C: out[t] = dot(h[t][:32], x_lin[t]) + lin_bias
// ============================================================================
__global__ void out_kernel(
    const float* __restrict__ x_lin,
    const float* __restrict__ lin_bias,
    float* __restrict__ out)
{
    int t = blockIdx.x * blockDim.x + threadIdx.x;
    if (t >= T_STEPS) return;
    const float4* h4 = (const float4*)(g_hbuf + (size_t)t * LINW);
    const float4* x4 = (const float4*)(x_lin + (size_t)t * LINW);
    float acc = 0.0f;
    #pragma unroll
    for (int q = 0; q < 8; q++) {
        float4 a = h4[q], b = x4[q];
        acc += a.x * b.x + a.y * b.y + a.z * b.z + a.w * b.w;
    }
    out[t] = acc + lin_bias[0];
}

// ============================================================================
extern "C" void kernel_launch(void* const* d_in, const int* in_sizes, int n_in,
                              void* d_out, int out_size)
{
    const float* in_gru   = (const float*)d_in[0];  // (T, 96)
    const float* in_lin   = (const float*)d_in[1];  // (T, 32)
    const float* init_h   = (const float*)d_in[2];  // (128,)
    const float* w_ih     = (const float*)d_in[3];  // (384, 96)
    const float* w_hh     = (const float*)d_in[4];  // (384, 128)
    const float* b_ih     = (const float*)d_in[5];  // (384,)
    const float* b_n      = (const float*)d_in[6];  // (128,)
    const float* lin_bias = (const float*)d_in[7];  // (1,)

    igates_kernel<<<T_STEPS / 64, 384>>>(in_gru, w_ih, b_ih);
    scan_kernel<<<2, 384>>>(init_h, w_hh, b_n);   // 1 cluster of 2 CTAs
    out_kernel<<<T_STEPS / 256, 256>>>(in_lin, lin_bias, (float*)d_out);
}

// round 9
// speedup vs baseline: 1.7329x; 1.7329x over previous
#include <cuda_runtime.h>
#include <cstdint>

#define T_STEPS 65536
#define HID     128
#define INS     96
#define LINW    32
#define G3      384   // 3 * HID

// Scratch (allocation-free rule: __device__ globals)
__device__ float g_igates[(size_t)(T_STEPS + 1) * G3];  // +1 row pad for the t+1 prefetch
__device__ float g_hbuf[(size_t)T_STEPS * LINW];

typedef unsigned long long ull;

// ---- packed f32x2 helpers (Blackwell sm_103a) ----
__device__ __forceinline__ ull pack2(float lo, float hi) {
    ull r; asm("mov.b64 %0,{%1,%2};" : "=l"(r) : "f"(lo), "f"(hi)); return r;
}
__device__ __forceinline__ void unpack2(ull p, float& lo, float& hi) {
    asm("mov.b64 {%0,%1},%2;" : "=f"(lo), "=f"(hi) : "l"(p));
}
__device__ __forceinline__ ull ffma2(ull a, ull b, ull c) {
    ull d; asm("fma.rn.f32x2 %0,%1,%2,%3;" : "=l"(d) : "l"(a), "l"(b), "l"(c)); return d;
}
__device__ __forceinline__ ull fadd2(ull a, ull b) {
    ull d; asm("add.rn.f32x2 %0,%1,%2;" : "=l"(d) : "l"(a), "l"(b)); return d;
}

// ---- fast, overflow-safe activations (err ~1e-6, well under 1e-3 budget) ----
__device__ __forceinline__ float fsigmoid(float x) {
    float e = __expf(-x);
    return __fdividef(1.0f, 1.0f + e);
}
__device__ __forceinline__ float ftanh_f(float x) {
    float ax = fabsf(x);
    float e  = __expf(-2.0f * ax);
    float t  = __fdividef(1.0f - e, 1.0f + e);
    return copysignf(t, x);
}

// ============================================================================
// Kernel A: igates[t][j] = b_ih[j] + sum_k input_GRU[t][k] * w_ih[j][k]
// 384 threads/block (one output column each), 64 timesteps per block.
// ============================================================================
__global__ __launch_bounds__(384, 1) void igates_kernel(
    const float* __restrict__ in_gru,
    const float* __restrict__ w_ih,
    const float* __restrict__ b_ih)
{
    __shared__ __align__(16) float s_in[64 * INS];
    const int tid = threadIdx.x;
    const int t0  = blockIdx.x * 64;

    {
        const float4* gsrc = (const float4*)(in_gru + (size_t)t0 * INS);
        float4* sdst = (float4*)s_in;
        for (int q = tid; q < (64 * INS) / 4; q += 384) sdst[q] = gsrc[q];
    }

    ull wq[48];
    {
        const float4* wr = (const float4*)(w_ih + (size_t)tid * INS);
        #pragma unroll
        for (int q = 0; q < 24; q++) {
            float4 v = wr[q];
            wq[2 * q]     = pack2(v.x, v.y);
            wq[2 * q + 1] = pack2(v.z, v.w);
        }
    }
    const float bias = b_ih[tid];
    __syncthreads();

    for (int tt = 0; tt < 64; tt++) {
        const ulonglong2* hp2 = (const ulonglong2*)(s_in + tt * INS);
        ull a0 = 0ull, a1 = 0ull, a2 = 0ull, a3 = 0ull;
        #pragma unroll
        for (int q = 0; q < 24; q++) {
            ulonglong2 hv = hp2[q];
            if (q & 1) { a2 = ffma2(wq[2 * q], hv.x, a2); a3 = ffma2(wq[2 * q + 1], hv.y, a3); }
            else       { a0 = ffma2(wq[2 * q], hv.x, a0); a1 = ffma2(wq[2 * q + 1], hv.y, a1); }
        }
        ull s = fadd2(fadd2(a0, a2), fadd2(a1, a3));
        float lo, hi; unpack2(s, lo, hi);
        g_igates[(size_t)(t0 + tt) * G3 + tid] = lo + hi + bias;
    }
}

// ============================================================================
// Kernel B: sequential scan. ONE CTA, 256 threads, single SM.
//
// Thread (j = tid>>1, half = tid&1) owns ALL THREE gate rows (r: j,
// z: 128+j, n: 256+j) of w_hh over columns [half*64, half*64+64) —
// 96 packed f32x2 weight registers. Per step:
//   - prefetch igates(t+1)  (LDG, consumed ~500 cyc later)
//   - FMA: 96 FFMA2/thread reading the h column-half via broadcast LDS.128
//     (h padded +16B so even/odd lane groups hit disjoint banks -> 1 wavefront)
//   - 3x shfl_xor(1): merge column halves -> full (hr,hz,hn) in EVERY thread
//   - activation computed redundantly by both halves (no exchange, no barrier)
//   - half==0 stores hnew to the OTHER h buffer (double-buffered -> no WAR)
//   - ONE __syncthreads per step
// ============================================================================
__global__ __launch_bounds__(256, 1) void scan_kernel(
    const float* __restrict__ init_h,
    const float* __restrict__ w_hh,
    const float* __restrict__ b_n)
{
    // h layout per buffer: cols 0..63 at floats [0,64); cols 64..127 at [68,132)
    __shared__ __align__(16) float h_sm[2][136];

    const int tid  = threadIdx.x;
    const int j    = tid >> 1;      // hidden unit 0..127
    const int half = tid & 1;       // column half
    const uint32_t hoff = half ? 272u : 0u;  // byte offset of this half in a buffer

    // weights: rows {j, 128+j, 256+j}, 64 columns each -> 96 packed f32x2
    ull wq[96];
    #pragma unroll
    for (int r = 0; r < 3; r++) {
        const float4* wr = (const float4*)(w_hh + (size_t)(r * HID + j) * HID + half * 64);
        #pragma unroll
        for (int q = 0; q < 16; q++) {
            float4 v = wr[q];
            wq[r * 32 + 2 * q]     = pack2(v.x, v.y);
            wq[r * 32 + 2 * q + 1] = pack2(v.z, v.w);
        }
    }

    // init h buffer 0 (padded layout)
    if (tid < HID) {
        int idx = tid + ((tid >> 6) << 2);
        h_sm[0][idx] = init_h[tid];
    }

    const int  jidx  = j + ((j >> 6) << 2);   // padded index of unit j
    const float bni  = b_n[j];
    float h_old = init_h[j];
    float ir  = g_igates[j];
    float iz  = g_igates[HID + j];
    float inq = g_igates[2 * HID + j];
    __syncthreads();

    for (int t = 0; t < T_STEPS; t++) {
        // ---- prefetch igates for step t+1 (hidden behind FMA phase) ----
        const float* nx = g_igates + (size_t)(t + 1) * G3 + j;
        float irn = nx[0];
        float izn = nx[HID];
        float inn = nx[2 * HID];

        // ---- FMA phase: 3 gate rows x this thread's 64-column half ----
        float hr, hz, hn;
        {
            const ulonglong2* hp =
                (const ulonglong2*)((const char*)&h_sm[t & 1][0] + hoff);
            ull a0 = 0ull, a1 = 0ull, a2 = 0ull, a3 = 0ull, a4 = 0ull, a5 = 0ull;
            #pragma unroll
            for (int q = 0; q < 16; q++) {
                ulonglong2 hv = hp[q];
                a0 = ffma2(wq[2 * q],          hv.x, a0);
                a1 = ffma2(wq[2 * q + 1],      hv.y, a1);
                a2 = ffma2(wq[32 + 2 * q],     hv.x, a2);
                a3 = ffma2(wq[32 + 2 * q + 1], hv.y, a3);
                a4 = ffma2(wq[64 + 2 * q],     hv.x, a4);
                a5 = ffma2(wq[64 + 2 * q + 1], hv.y, a5);
            }
            float lo, hi, p;
            ull s;
            s = fadd2(a0, a1); unpack2(s, lo, hi); p = lo + hi;
            hr = p + __shfl_xor_sync(0xFFFFFFFFu, p, 1);
            s = fadd2(a2, a3); unpack2(s, lo, hi); p = lo + hi;
            hz = p + __shfl_xor_sync(0xFFFFFFFFu, p, 1);
            s = fadd2(a4, a5); unpack2(s, lo, hi); p = lo + hi;
            hn = p + __shfl_xor_sync(0xFFFFFFFFu, p, 1);
        }

        // ---- activation (redundant across both halves; no divergence) ----
        float r = fsigmoid(ir + hr);
        float z = fsigmoid(iz + hz);
        float n = ftanh_f(inq + r * (hn + bni));
        float hnew = n + z * (h_old - n);               // equinox GRUCell
        h_old = hnew;

        if (half == 0) {
            h_sm[(t + 1) & 1][jidx] = hnew;             // double-buffered h
            if (j < LINW) g_hbuf[(size_t)t * LINW + j] = hnew;  // off critical path
        }
        ir = irn; iz = izn; inq = inn;

        __syncthreads();   // single barrier per step: h[b^1] ready for all
    }
}

// ============================================================================
// Kernel C: out[t] = dot(h[t][:32], x_lin[t]) + lin_bias
// ============================================================================
__global__ void out_kernel(
    const float* __restrict__ x_lin,
    const float* __restrict__ lin_bias,
    float* __restrict__ out)
{
    int t = blockIdx.x * blockDim.x + threadIdx.x;
    if (t >= T_STEPS) return;
    const float4* h4 = (const float4*)(g_hbuf + (size_t)t * LINW);
    const float4* x4 = (const float4*)(x_lin + (size_t)t * LINW);
    float acc = 0.0f;
    #pragma unroll
    for (int q = 0; q < 8; q++) {
        float4 a = h4[q], b = x4[q];
        acc += a.x * b.x + a.y * b.y + a.z * b.z + a.w * b.w;
    }
    out[t] = acc + lin_bias[0];
}

// ============================================================================
extern "C" void kernel_launch(void* const* d_in, const int* in_sizes, int n_in,
                              void* d_out, int out_size)
{
    const float* in_gru   = (const float*)d_in[0];  // (T, 96)
    const float* in_lin   = (const float*)d_in[1];  // (T, 32)
    const float* init_h   = (const float*)d_in[2];  // (128,)
    const float* w_ih     = (const float*)d_in[3];  // (384, 96)
    const float* w_hh     = (const float*)d_in[4];  // (384, 128)
    const float* b_ih     = (const float*)d_in[5];  // (384,)
    const float* b_n      = (const float*)d_in[6];  // (128,)
    const float* lin_bias = (const float*)d_in[7];  // (1,)

    igates_kernel<<<T_STEPS / 64, 384>>>(in_gru, w_ih, b_ih);
    scan_kernel<<<1, 256>>>(init_h, w_hh, b_n);
    out_kernel<<<T_STEPS / 256, 256>>>(in_lin, lin_bias, (float*)d_out);
}

// round 11
// speedup vs baseline: 1.8194x; 1.0499x over previous
#include <cuda_runtime.h>
#include <cstdint>

#define T_STEPS 65536
#define HID     128
#define INS     96
#define LINW    32
#define G3      384   // 3 * HID

// Scratch (allocation-free rule: __device__ globals)
__device__ float g_igates[(size_t)(T_STEPS + 1) * G3];  // +1 row pad for the t+1 prefetch
__device__ float g_hbuf[(size_t)T_STEPS * LINW];

typedef unsigned long long ull;

// ---- packed f32x2 helpers (Blackwell sm_103a) ----
__device__ __forceinline__ ull pack2(float lo, float hi) {
    ull r; asm("mov.b64 %0,{%1,%2};" : "=l"(r) : "f"(lo), "f"(hi)); return r;
}
__device__ __forceinline__ void unpack2(ull p, float& lo, float& hi) {
    asm("mov.b64 {%0,%1},%2;" : "=f"(lo), "=f"(hi) : "l"(p));
}
__device__ __forceinline__ ull ffma2(ull a, ull b, ull c) {
    ull d; asm("fma.rn.f32x2 %0,%1,%2,%3;" : "=l"(d) : "l"(a), "l"(b), "l"(c)); return d;
}
__device__ __forceinline__ ull fadd2(ull a, ull b) {
    ull d; asm("add.rn.f32x2 %0,%1,%2;" : "=l"(d) : "l"(a), "l"(b)); return d;
}

// ---- fast, overflow-safe activations (err ~1e-6, well under 1e-3 budget) ----
__device__ __forceinline__ float fsigmoid(float x) {
    float e = __expf(-x);
    return __fdividef(1.0f, 1.0f + e);
}
__device__ __forceinline__ float ftanh_f(float x) {
    float ax = fabsf(x);
    float e  = __expf(-2.0f * ax);
    float t  = __fdividef(1.0f - e, 1.0f + e);
    return copysignf(t, x);
}

// ============================================================================
// Kernel A: igates[t][j] = b_ih[j] + sum_k input_GRU[t][k] * w_ih[j][k]
// ============================================================================
__global__ __launch_bounds__(384, 1) void igates_kernel(
    const float* __restrict__ in_gru,
    const float* __restrict__ w_ih,
    const float* __restrict__ b_ih)
{
    __shared__ __align__(16) float s_in[64 * INS];
    const int tid = threadIdx.x;
    const int t0  = blockIdx.x * 64;

    {
        const float4* gsrc = (const float4*)(in_gru + (size_t)t0 * INS);
        float4* sdst = (float4*)s_in;
        for (int q = tid; q < (64 * INS) / 4; q += 384) sdst[q] = gsrc[q];
    }

    ull wq[48];
    {
        const float4* wr = (const float4*)(w_ih + (size_t)tid * INS);
        #pragma unroll
        for (int q = 0; q < 24; q++) {
            float4 v = wr[q];
            wq[2 * q]     = pack2(v.x, v.y);
            wq[2 * q + 1] = pack2(v.z, v.w);
        }
    }
    const float bias = b_ih[tid];
    __syncthreads();

    for (int tt = 0; tt < 64; tt++) {
        const ulonglong2* hp2 = (const ulonglong2*)(s_in + tt * INS);
        ull a0 = 0ull, a1 = 0ull, a2 = 0ull, a3 = 0ull;
        #pragma unroll
        for (int q = 0; q < 24; q++) {
            ulonglong2 hv = hp2[q];
            if (q & 1) { a2 = ffma2(wq[2 * q], hv.x, a2); a3 = ffma2(wq[2 * q + 1], hv.y, a3); }
            else       { a0 = ffma2(wq[2 * q], hv.x, a0); a1 = ffma2(wq[2 * q + 1], hv.y, a1); }
        }
        ull s = fadd2(fadd2(a0, a2), fadd2(a1, a3));
        float lo, hi; unpack2(s, lo, hi);
        g_igates[(size_t)(t0 + tt) * G3 + tid] = lo + hi + bias;
    }
}

// ============================================================================
// Kernel B: sequential scan. ONE CTA, 256 threads, single SM.
//
// Thread (j = tid>>1, half = tid&1) owns gate rows {j, 128+j, 256+j} of w_hh
// over columns [half*64, half*64+64).
//
// Latency-split schedule per step:
//   pass 1: r- and z-gate chains (64 FFMA2) -> reduce -> shfl -> sigmoid
//           (the ~100-cycle r/z reduce+shfl+MUFU chains DRAIN UNDER pass 2)
//   pass 2: n-gate chain (32 FFMA2, h re-read from SMEM broadcast)
//   tail:   n-reduce + shfl + tanh + hnew + STS + one __syncthreads
// h double-buffered in SMEM (+16B pad: even/odd lane broadcast groups hit
// disjoint banks -> 1 wavefront per LDS.128).
// ============================================================================
__global__ __launch_bounds__(256, 1) void scan_kernel(
    const float* __restrict__ init_h,
    const float* __restrict__ w_hh,
    const float* __restrict__ b_n)
{
    // h layout per buffer: cols 0..63 at floats [0,64); cols 64..127 at [68,132)
    __shared__ __align__(16) float h_sm[2][136];

    const int tid  = threadIdx.x;
    const int j    = tid >> 1;      // hidden unit 0..127
    const int half = tid & 1;       // column half
    const uint32_t hoff = half ? 272u : 0u;

    // weights: rows {j, 128+j, 256+j}, this thread's 64 columns each
    ull wr_[32], wz_[32], wn_[32];
    {
        const float4* p;
        p = (const float4*)(w_hh + (size_t)(0 * HID + j) * HID + half * 64);
        #pragma unroll
        for (int q = 0; q < 16; q++) { float4 v = p[q]; wr_[2*q] = pack2(v.x,v.y); wr_[2*q+1] = pack2(v.z,v.w); }
        p = (const float4*)(w_hh + (size_t)(1 * HID + j) * HID + half * 64);
        #pragma unroll
        for (int q = 0; q < 16; q++) { float4 v = p[q]; wz_[2*q] = pack2(v.x,v.y); wz_[2*q+1] = pack2(v.z,v.w); }
        p = (const float4*)(w_hh + (size_t)(2 * HID + j) * HID + half * 64);
        #pragma unroll
        for (int q = 0; q < 16; q++) { float4 v = p[q]; wn_[2*q] = pack2(v.x,v.y); wn_[2*q+1] = pack2(v.z,v.w); }
    }

    // init h buffer 0 (padded layout)
    if (tid < HID) {
        int idx = tid + ((tid >> 6) << 2);
        h_sm[0][idx] = init_h[tid];
    }

    const int  jidx = j + ((j >> 6) << 2);
    const float bni = b_n[j];
    float h_old = init_h[j];
    float ir  = g_igates[j];
    float iz  = g_igates[HID + j];
    float inq = g_igates[2 * HID + j];
    __syncthreads();

    for (int t = 0; t < T_STEPS; t++) {
        // prefetch igates for step t+1 (DRAM latency hidden behind both passes)
        const float* nx = g_igates + (size_t)(t + 1) * G3 + j;
        float irn = nx[0];
        float izn = nx[HID];
        float inn = nx[2 * HID];

        const ulonglong2* hp =
            (const ulonglong2*)((const char*)&h_sm[t & 1][0] + hoff);

        // ---- pass 1: r and z gate chains ----
        float r, z;
        {
            ull a0 = 0ull, a1 = 0ull, a2 = 0ull, a3 = 0ull;
            #pragma unroll
            for (int q = 0; q < 16; q++) {
                ulonglong2 hv = hp[q];
                a0 = ffma2(wr_[2 * q],     hv.x, a0);
                a1 = ffma2(wr_[2 * q + 1], hv.y, a1);
                a2 = ffma2(wz_[2 * q],     hv.x, a2);
                a3 = ffma2(wz_[2 * q + 1], hv.y, a3);
            }
            float lo, hi, p;
            ull s;
            s = fadd2(a0, a1); unpack2(s, lo, hi); p = lo + hi;
            float hr = p + __shfl_xor_sync(0xFFFFFFFFu, p, 1);
            r = fsigmoid(ir + hr);                 // MUFU chain drains under pass 2
            s = fadd2(a2, a3); unpack2(s, lo, hi); p = lo + hi;
            float hz = p + __shfl_xor_sync(0xFFFFFFFFu, p, 1);
            z = fsigmoid(iz + hz);                 // ditto
        }

        // ---- pass 2: n gate chain (h re-read: broadcast LDS, LSU pipe idle) ----
        float hn;
        {
            ull b0 = 0ull, b1 = 0ull, b2 = 0ull, b3 = 0ull;
            #pragma unroll
            for (int q = 0; q < 16; q += 2) {
                ulonglong2 hv0 = hp[q];
                ulonglong2 hv1 = hp[q + 1];
                b0 = ffma2(wn_[2 * q],     hv0.x, b0);
                b1 = ffma2(wn_[2 * q + 1], hv0.y, b1);
                b2 = ffma2(wn_[2 * q + 2], hv1.x, b2);
                b3 = ffma2(wn_[2 * q + 3], hv1.y, b3);
            }
            ull s = fadd2(fadd2(b0, b2), fadd2(b1, b3));
            float lo, hi; unpack2(s, lo, hi);
            float p = lo + hi;
            hn = p + __shfl_xor_sync(0xFFFFFFFFu, p, 1);
        }

        // ---- tail: candidate + update (short, exact) ----
        float n    = ftanh_f(fmaf(r, hn + bni, inq));
        float hnew = n + z * (h_old - n);               // equinox GRUCell
        h_old = hnew;

        if (half == 0) {
            h_sm[(t + 1) & 1][jidx] = hnew;             // double-buffered h
            if (j < LINW) g_hbuf[(size_t)t * LINW + j] = hnew;
        }
        ir = irn; iz = izn; inq = inn;

        __syncthreads();   // single barrier per step
    }
}

// ============================================================================
// Kernel C: out[t] = dot(h[t][:32], x_lin[t]) + lin_bias
// ============================================================================
__global__ void out_kernel(
    const float* __restrict__ x_lin,
    const float* __restrict__ lin_bias,
    float* __restrict__ out)
{
    int t = blockIdx.x * blockDim.x + threadIdx.x;
    if (t >= T_STEPS) return;
    const float4* h4 = (const float4*)(g_hbuf + (size_t)t * LINW);
    const float4* x4 = (const float4*)(x_lin + (size_t)t * LINW);
    float acc = 0.0f;
    #pragma unroll
    for (int q = 0; q < 8; q++) {
        float4 a = h4[q], b = x4[q];
        acc += a.x * b.x + a.y * b.y + a.z * b.z + a.w * b.w;
    }
    out[t] = acc + lin_bias[0];
}

// ============================================================================
extern "C" void kernel_launch(void* const* d_in, const int* in_sizes, int n_in,
                              void* d_out, int out_size)
{
    const float* in_gru   = (const float*)d_in[0];  // (T, 96)
    const float* in_lin   = (const float*)d_in[1];  // (T, 32)
    const float* init_h   = (const float*)d_in[2];  // (128,)
    const float* w_ih     = (const float*)d_in[3];  // (384, 96)
    const float* w_hh     = (const float*)d_in[4];  // (384, 128)
    const float* b_ih     = (const float*)d_in[5];  // (384,)
    const float* b_n      = (const float*)d_in[6];  // (128,)
    const float* lin_bias = (const float*)d_in[7];  // (1,)

    igates_kernel<<<T_STEPS / 64, 384>>>(in_gru, w_ih, b_ih);
    scan_kernel<<<1, 256>>>(init_h, w_hh, b_n);
    out_kernel<<<T_STEPS / 256, 256>>>(in_lin, lin_bias, (float*)d_out);
}